// round 8
// baseline (speedup 1.0000x reference)
#include <cuda_runtime.h>
#include <cstdint>
#include <cstdio>

// Problem-size capacities (from reference setup: N=20000, E=320000)
#define NMAXN 20000
#define EMAXE 320000
#define ETOT  (NMAXN + EMAXE)

// ---------------- static device scratch (no allocations allowed) ----------------
// g_deg is SELF-RESTORING: zero-initialized at load, and k_scan2 re-zeroes it
// after consuming it, so every kernel_launch call starts from the same state.
__device__ __align__(16) float g_xl1[NMAXN * 256];
__device__ __align__(16) float g_xr1[NMAXN * 256];
__device__ __align__(16) float g_h1 [NMAXN * 256];
__device__ __align__(16) float g_xl2[NMAXN * 64];
__device__ __align__(16) float g_xr2[NMAXN * 64];
__device__ __align__(16) float g_h2 [NMAXN * 64];
__device__ int   g_deg[NMAXN];         // starts zeroed; restored by k_scan2
__device__ int   g_off[NMAXN + 1];
__device__ int   g_cur[NMAXN];
__device__ int   g_csrc[ETOT];
__device__ float g_sum[64];
__device__ float g_sumsq[64];

// ---------------- CSR build (by dst), E edges, 4 edges/thread ----------------
__global__ void k_count(const int* __restrict__ ei, int E) {
    int i0 = (blockIdx.x * blockDim.x + threadIdx.x) * 4;
    if (i0 + 4 <= E && ((E & 3) == 0)) {
        int4 d = *reinterpret_cast<const int4*>(ei + E + i0);
        atomicAdd(&g_deg[d.x], 1);
        atomicAdd(&g_deg[d.y], 1);
        atomicAdd(&g_deg[d.z], 1);
        atomicAdd(&g_deg[d.w], 1);
    } else {
        #pragma unroll
        for (int j = 0; j < 4; j++) {
            int i = i0 + j;
            if (i < E) atomicAdd(&g_deg[__ldg(ei + E + i)], 1);
        }
    }
}

// single-block chunked scan of (g_deg[i] + 1) -> offsets (self-loop folded in).
// Writes the self-loop into slot 0, sets g_cur = off + 1, zeroes g_deg behind
// itself, and zeroes the InstanceNorm accumulators.
#define SCAN_PER ((NMAXN + 1023) / 1024)
__global__ __launch_bounds__(1024) void k_scan2(int N) {
    __shared__ int sh[1024];
    int tid = threadIdx.x;
    if (tid < 64) { g_sum[tid] = 0.f; g_sumsq[tid] = 0.f; }
    int base = tid * SCAN_PER;
    int vals[SCAN_PER];
    int s = 0;
    #pragma unroll
    for (int i = 0; i < SCAN_PER; i++) {
        int idx = base + i;
        int v = 0;
        if (idx < N) {
            v = g_deg[idx] + 1;      // +1 = self-loop
            g_deg[idx] = 0;          // restore for next call
        }
        vals[i] = s;                 // exclusive within chunk
        s += v;
    }
    sh[tid] = s;
    __syncthreads();
    #pragma unroll
    for (int o = 1; o < 1024; o <<= 1) {
        int t = (tid >= o) ? sh[tid - o] : 0;
        __syncthreads();
        sh[tid] += t;
        __syncthreads();
    }
    int block_excl = sh[tid] - s;
    #pragma unroll
    for (int i = 0; i < SCAN_PER; i++) {
        int idx = base + i;
        if (idx < N) {
            int o = block_excl + vals[i];
            g_off[idx] = o;
            g_csrc[o] = idx;         // self-loop occupies slot 0
            g_cur[idx] = o + 1;
        }
    }
    if (tid == 1023) g_off[N] = sh[1023];
}

__global__ void k_fill(const int* __restrict__ ei, int E) {
    int i0 = (blockIdx.x * blockDim.x + threadIdx.x) * 4;
    if (i0 + 4 <= E && ((E & 3) == 0)) {
        int4 sv = *reinterpret_cast<const int4*>(ei + i0);
        int4 dv = *reinterpret_cast<const int4*>(ei + E + i0);
        int p0 = atomicAdd(&g_cur[dv.x], 1);
        int p1 = atomicAdd(&g_cur[dv.y], 1);
        int p2 = atomicAdd(&g_cur[dv.z], 1);
        int p3 = atomicAdd(&g_cur[dv.w], 1);
        g_csrc[p0] = sv.x;
        g_csrc[p1] = sv.y;
        g_csrc[p2] = sv.z;
        g_csrc[p3] = sv.w;
    } else {
        #pragma unroll
        for (int j = 0; j < 4; j++) {
            int i = i0 + j;
            if (i < E) {
                int src = __ldg(ei + i);
                int dst = __ldg(ei + E + i);
                int pos = atomicAdd(&g_cur[dst], 1);
                g_csrc[pos] = src;
            }
        }
    }
}

// ---------------- tf32 tensor-core GEMM, cp.async double-buffered ----------------
__device__ __forceinline__ unsigned f2tf32(float f) {
    unsigned u;
    asm("cvt.rna.tf32.f32 %0, %1;" : "=r"(u) : "f"(f));
    return u;
}

__device__ __forceinline__ void mma_tf32(float* d, const unsigned* a, unsigned b0, unsigned b1) {
    asm volatile(
        "mma.sync.aligned.m16n8k8.row.col.f32.tf32.tf32.f32 "
        "{%0,%1,%2,%3}, {%4,%5,%6,%7}, {%8,%9}, {%0,%1,%2,%3};"
        : "+f"(d[0]), "+f"(d[1]), "+f"(d[2]), "+f"(d[3])
        : "r"(a[0]), "r"(a[1]), "r"(a[2]), "r"(a[3]), "r"(b0), "r"(b1));
}

__device__ __forceinline__ void cp_async16(uint32_t saddr, const void* g, int srcbytes) {
    asm volatile("cp.async.cg.shared.global [%0], [%1], 16, %2;"
                 :: "r"(saddr), "l"(g), "r"(srcbytes));
}

#define AS_STRIDE 36
#define BS_STRIDE 136
#define AS_STAGE  (64 * AS_STRIDE)
#define BS_STAGE  (32 * BS_STRIDE)
#define SMEM_MMA_BYTES ((2 * AS_STAGE + 2 * BS_STAGE) * 4)

__global__ __launch_bounds__(256) void k_mma(
    const float* __restrict__ A,
    const float* __restrict__ B0, const float* __restrict__ B1,
    float* __restrict__ C0, float* __restrict__ C1,
    int M, int K, int H)
{
    extern __shared__ float smem[];
    float* sAs = smem;                       // [2][64][36]
    float* sBs = smem + 2 * AS_STAGE;        // [2][32][136]

    int tid = threadIdx.x;
    int lane = tid & 31, warp = tid >> 5;
    int wm = warp & 1, wn = warp >> 1;       // 2 x 4 warp grid
    int m0 = blockIdx.x * 64;
    int n0g = blockIdx.y * 128;              // col in concatenated [0, 2H) space
    int g = lane >> 2, tg = lane & 3;

    float acc[2][4][4];
    #pragma unroll
    for (int mt = 0; mt < 2; mt++)
        #pragma unroll
        for (int nt = 0; nt < 4; nt++)
            #pragma unroll
            for (int i = 0; i < 4; i++) acc[mt][nt][i] = 0.f;

    int ar = tid >> 2;          // 0..63
    int ac = (tid & 3) * 8;     // 0,8,16,24
    int br = tid >> 3;          // 0..31
    int bc = (tid & 7) * 16;    // 0..112

    int arow = m0 + ar;
    int apred = (arow < M) ? 16 : 0;
    if (arow >= M) arow = M - 1;
    const float* abase = A + (size_t)arow * K + ac;

    const float* bsrc[4];
    #pragma unroll
    for (int i = 0; i < 4; i++) {
        int col = n0g + bc + i * 4;
        bsrc[i] = (col < H) ? (B0 + (size_t)br * H + col)
                            : (B1 + (size_t)br * H + (col - H));
    }

    uint32_t sA0 = (uint32_t)__cvta_generic_to_shared(sAs);
    uint32_t sB0 = (uint32_t)__cvta_generic_to_shared(sBs);

    int nIter = K >> 5;

    auto load_stage = [&](int k0, int st) {
        uint32_t sa = sA0 + (st * AS_STAGE + ar * AS_STRIDE + ac) * 4;
        const float* ap = abase + k0;
        cp_async16(sa,      ap,     apred);
        cp_async16(sa + 16, ap + 4, apred);
        uint32_t sb = sB0 + (st * BS_STAGE + br * BS_STRIDE + bc) * 4;
        size_t koff = (size_t)k0 * H;
        #pragma unroll
        for (int i = 0; i < 4; i++)
            cp_async16(sb + i * 16, bsrc[i] + koff, 16);
    };

    load_stage(0, 0);
    asm volatile("cp.async.commit_group;" ::: "memory");

    for (int it = 0; it < nIter; it++) {
        int st = it & 1;
        asm volatile("cp.async.wait_group 0;" ::: "memory");
        __syncthreads();
        if (it + 1 < nIter) {
            load_stage((it + 1) << 5, st ^ 1);
            asm volatile("cp.async.commit_group;" ::: "memory");
        }

        const float* As = sAs + st * AS_STAGE;
        const float* Bs = sBs + st * BS_STAGE;

        #pragma unroll
        for (int kk = 0; kk < 32; kk += 8) {
            unsigned afr[2][4];
            #pragma unroll
            for (int mt = 0; mt < 2; mt++) {
                int row = wm * 32 + mt * 16;
                afr[mt][0] = f2tf32(As[(row + g    ) * AS_STRIDE + kk + tg    ]);
                afr[mt][1] = f2tf32(As[(row + g + 8) * AS_STRIDE + kk + tg    ]);
                afr[mt][2] = f2tf32(As[(row + g    ) * AS_STRIDE + kk + tg + 4]);
                afr[mt][3] = f2tf32(As[(row + g + 8) * AS_STRIDE + kk + tg + 4]);
            }
            #pragma unroll
            for (int nt = 0; nt < 4; nt++) {
                int ncol = wn * 32 + nt * 8;
                unsigned b0 = f2tf32(Bs[(kk + tg    ) * BS_STRIDE + ncol + g]);
                unsigned b1 = f2tf32(Bs[(kk + tg + 4) * BS_STRIDE + ncol + g]);
                #pragma unroll
                for (int mt = 0; mt < 2; mt++)
                    mma_tf32(acc[mt][nt], afr[mt], b0, b1);
            }
        }
        __syncthreads();
    }

    #pragma unroll
    for (int mt = 0; mt < 2; mt++) {
        int r0 = m0 + wm * 32 + mt * 16 + g;
        #pragma unroll
        for (int nt = 0; nt < 4; nt++) {
            int col = n0g + wn * 32 + nt * 8 + tg * 2;
            float* Cp = C0;
            int c = col;
            if (col >= H) { Cp = C1; c = col - H; }
            if (r0 < M)
                *reinterpret_cast<float2*>(Cp + (size_t)r0 * H + c) =
                    make_float2(acc[mt][nt][0], acc[mt][nt][1]);
            if (r0 + 8 < M)
                *reinterpret_cast<float2*>(Cp + (size_t)(r0 + 8) * H + c) =
                    make_float2(acc[mt][nt][2], acc[mt][nt][3]);
        }
    }
}

// ---------------- vector load helper ----------------
template <int V>
__device__ __forceinline__ void loadv(float* d, const float* __restrict__ p) {
    if constexpr (V == 8) {
        float4 a = *reinterpret_cast<const float4*>(p);
        float4 b = *reinterpret_cast<const float4*>(p + 4);
        d[0] = a.x; d[1] = a.y; d[2] = a.z; d[3] = a.w;
        d[4] = b.x; d[5] = b.y; d[6] = b.z; d[7] = b.w;
    } else if constexpr (V == 2) {
        float2 a = *reinterpret_cast<const float2*>(p);
        d[0] = a.x; d[1] = a.y;
    } else {
        #pragma unroll
        for (int j = 0; j < V; j++) d[j] = p[j];
    }
}

// ---------------- GATv2 node aggregation: warp per node, online softmax ----------------
// 4-edge unrolled mainloop (4 rows in flight), 2-edge then 1-edge tails.
template <int HC, int VPT, int REDW, bool ELU_ACT, bool STATS>
__global__ __launch_bounds__(256) void k_node_agg(
    const float* __restrict__ xl, const float* __restrict__ xr,
    const float* __restrict__ att, const float* __restrict__ bias,
    float* __restrict__ outp, int N)
{
    __shared__ float sh_sum[STATS ? 64 : 1];
    __shared__ float sh_sq [STATS ? 64 : 1];
    int tid = threadIdx.x;
    if (STATS) {
        if (tid < 64) { sh_sum[tid] = 0.f; sh_sq[tid] = 0.f; }
        __syncthreads();
    }

    int warp = (blockIdx.x * blockDim.x + tid) >> 5;
    int lane = tid & 31;
    bool active = warp < N;
    int c0 = lane * VPT;

    if (active) {
        int n = warp;
        float xrv[VPT], attv[VPT], acc[VPT];
        loadv<VPT>(xrv, xr + (size_t)n * HC + c0);
        loadv<VPT>(attv, att + c0);
        #pragma unroll
        for (int j = 0; j < VPT; j++) acc[j] = 0.f;

        float m = __int_as_float(0xff800000);   // -inf
        float denom = 0.f;

        int s = g_off[n], e = g_off[n + 1];
        int i = s;

        for (; i + 4 <= e; i += 4) {
            int s0 = g_csrc[i], s1 = g_csrc[i + 1];
            int s2 = g_csrc[i + 2], s3 = g_csrc[i + 3];
            float x0[VPT], x1[VPT], x2[VPT], x3[VPT];
            loadv<VPT>(x0, xl + (size_t)s0 * HC + c0);
            loadv<VPT>(x1, xl + (size_t)s1 * HC + c0);
            loadv<VPT>(x2, xl + (size_t)s2 * HC + c0);
            loadv<VPT>(x3, xl + (size_t)s3 * HC + c0);

            float sc0 = 0.f, sc1 = 0.f, sc2 = 0.f, sc3 = 0.f;
            #pragma unroll
            for (int j = 0; j < VPT; j++) {
                float t0 = x0[j] + xrv[j], t1 = x1[j] + xrv[j];
                float t2 = x2[j] + xrv[j], t3 = x3[j] + xrv[j];
                t0 = (t0 > 0.f) ? t0 : 0.2f * t0;
                t1 = (t1 > 0.f) ? t1 : 0.2f * t1;
                t2 = (t2 > 0.f) ? t2 : 0.2f * t2;
                t3 = (t3 > 0.f) ? t3 : 0.2f * t3;
                sc0 = fmaf(t0, attv[j], sc0);
                sc1 = fmaf(t1, attv[j], sc1);
                sc2 = fmaf(t2, attv[j], sc2);
                sc3 = fmaf(t3, attv[j], sc3);
            }
            #pragma unroll
            for (int w = 1; w < REDW; w <<= 1) {
                sc0 += __shfl_xor_sync(0xffffffffu, sc0, w);
                sc1 += __shfl_xor_sync(0xffffffffu, sc1, w);
                sc2 += __shfl_xor_sync(0xffffffffu, sc2, w);
                sc3 += __shfl_xor_sync(0xffffffffu, sc3, w);
            }

            float newm = fmaxf(fmaxf(m, fmaxf(sc0, sc1)), fmaxf(sc2, sc3));
            float r  = __expf(m - newm);       // 0 on first iter (m = -inf)
            float e0 = __expf(sc0 - newm);
            float e1 = __expf(sc1 - newm);
            float e2 = __expf(sc2 - newm);
            float e3 = __expf(sc3 - newm);
            denom = fmaf(denom, r, (e0 + e1) + (e2 + e3));
            #pragma unroll
            for (int j = 0; j < VPT; j++) {
                float t = fmaf(e0, x0[j], e1 * x1[j]);
                t = fmaf(e2, x2[j], t);
                t = fmaf(e3, x3[j], t);
                acc[j] = fmaf(acc[j], r, t);
            }
            m = newm;
        }

        for (; i + 2 <= e; i += 2) {
            int s0 = g_csrc[i], s1 = g_csrc[i + 1];
            float x0[VPT], x1[VPT];
            loadv<VPT>(x0, xl + (size_t)s0 * HC + c0);
            loadv<VPT>(x1, xl + (size_t)s1 * HC + c0);

            float sc0 = 0.f, sc1 = 0.f;
            #pragma unroll
            for (int j = 0; j < VPT; j++) {
                float t0 = x0[j] + xrv[j], t1 = x1[j] + xrv[j];
                t0 = (t0 > 0.f) ? t0 : 0.2f * t0;
                t1 = (t1 > 0.f) ? t1 : 0.2f * t1;
                sc0 = fmaf(t0, attv[j], sc0);
                sc1 = fmaf(t1, attv[j], sc1);
            }
            #pragma unroll
            for (int w = 1; w < REDW; w <<= 1) {
                sc0 += __shfl_xor_sync(0xffffffffu, sc0, w);
                sc1 += __shfl_xor_sync(0xffffffffu, sc1, w);
            }
            float newm = fmaxf(m, fmaxf(sc0, sc1));
            float r  = __expf(m - newm);
            float e0 = __expf(sc0 - newm);
            float e1 = __expf(sc1 - newm);
            denom = fmaf(denom, r, e0 + e1);
            #pragma unroll
            for (int j = 0; j < VPT; j++)
                acc[j] = fmaf(acc[j], r, fmaf(e0, x0[j], e1 * x1[j]));
            m = newm;
        }

        if (i < e) {
            int src = g_csrc[i];
            float xlv[VPT];
            loadv<VPT>(xlv, xl + (size_t)src * HC + c0);
            float sc = 0.f;
            #pragma unroll
            for (int j = 0; j < VPT; j++) {
                float t = xlv[j] + xrv[j];
                t = (t > 0.f) ? t : 0.2f * t;
                sc = fmaf(t, attv[j], sc);
            }
            #pragma unroll
            for (int w = 1; w < REDW; w <<= 1)
                sc += __shfl_xor_sync(0xffffffffu, sc, w);
            if (sc > m) {
                float r = __expf(m - sc);
                denom *= r;
                #pragma unroll
                for (int j = 0; j < VPT; j++) acc[j] *= r;
                m = sc;
            }
            float ex = __expf(sc - m);
            denom += ex;
            #pragma unroll
            for (int j = 0; j < VPT; j++) acc[j] = fmaf(ex, xlv[j], acc[j]);
        }

        float inv = 1.f / (denom + 1e-16f);
        #pragma unroll
        for (int j = 0; j < VPT; j++) {
            float v = acc[j] * inv + bias[c0 + j];
            if (ELU_ACT) v = (v > 0.f) ? v : (__expf(v) - 1.f);  // ELU alpha=1
            outp[(size_t)n * HC + c0 + j] = v;
            if (STATS) {
                atomicAdd(&sh_sum[c0 + j], v);
                atomicAdd(&sh_sq [c0 + j], v * v);
            }
        }
    }

    if (STATS) {
        __syncthreads();
        if (tid < 64) {
            atomicAdd(&g_sum[tid],   sh_sum[tid]);
            atomicAdd(&g_sumsq[tid], sh_sq[tid]);
        }
    }
}

// ---------------- InstanceNorm + log_softmax epilogue (warp per node) ----------------
__global__ __launch_bounds__(256) void k_final(
    const float* __restrict__ h,
    const float* __restrict__ gamma, const float* __restrict__ beta,
    float* __restrict__ out, int N)
{
    int gw = (blockIdx.x * blockDim.x + threadIdx.x) >> 5;
    int lane = threadIdx.x & 31;
    if (gw >= N) return;
    int c0 = lane * 2;

    float2 x = *reinterpret_cast<const float2*>(h + (size_t)gw * 64 + c0);
    float invN = 1.f / (float)N;

    float mean0 = g_sum[c0] * invN;
    float var0  = g_sumsq[c0] * invN - mean0 * mean0;
    float y0 = (x.x - mean0) * rsqrtf(var0 + 1e-5f) * gamma[c0] + beta[c0];

    float mean1 = g_sum[c0 + 1] * invN;
    float var1  = g_sumsq[c0 + 1] * invN - mean1 * mean1;
    float y1 = (x.y - mean1) * rsqrtf(var1 + 1e-5f) * gamma[c0 + 1] + beta[c0 + 1];

    float2 yv = make_float2(y0, y1);
    *reinterpret_cast<float2*>(out + (size_t)gw * 64 + c0) = yv;

    float mx = fmaxf(y0, y1);
    #pragma unroll
    for (int w = 1; w < 32; w <<= 1) mx = fmaxf(mx, __shfl_xor_sync(0xffffffffu, mx, w));
    float se = __expf(y0 - mx) + __expf(y1 - mx);
    #pragma unroll
    for (int w = 1; w < 32; w <<= 1) se += __shfl_xor_sync(0xffffffffu, se, w);
    float ls = __logf(se) + mx;          // log-sum-exp

    float2 lv = make_float2(y0 - ls, y1 - ls);
    *reinterpret_cast<float2*>(out + (size_t)N * 64 + (size_t)gw * 64 + c0) = lv;
}

// ---------------- host launcher ----------------
extern "C" void kernel_launch(void* const* d_in, const int* in_sizes, int n_in,
                              void* d_out, int out_size)
{
    const float* x     = (const float*)d_in[0];
    const float* Wl1   = (const float*)d_in[1];
    const float* Wr1   = (const float*)d_in[2];
    const float* att1  = (const float*)d_in[3];
    const float* b1    = (const float*)d_in[4];
    const float* Wl2   = (const float*)d_in[5];
    const float* Wr2   = (const float*)d_in[6];
    const float* att2  = (const float*)d_in[7];
    const float* b2    = (const float*)d_in[8];
    const float* gamma = (const float*)d_in[9];
    const float* beta  = (const float*)d_in[10];
    const int*   ei    = (const int*)  d_in[11];   // [2, E] int32

    int N = in_sizes[0] / 128;
    int E = in_sizes[11] / 2;

    void *p;
    cudaGetSymbolAddress(&p, g_xl1); float* xl1 = (float*)p;
    cudaGetSymbolAddress(&p, g_xr1); float* xr1 = (float*)p;
    cudaGetSymbolAddress(&p, g_h1 ); float* h1  = (float*)p;
    cudaGetSymbolAddress(&p, g_xl2); float* xl2 = (float*)p;
    cudaGetSymbolAddress(&p, g_xr2); float* xr2 = (float*)p;
    cudaGetSymbolAddress(&p, g_h2 ); float* h2  = (float*)p;

    static bool attr_set = false;
    if (!attr_set) {
        cudaFuncSetAttribute(k_mma, cudaFuncAttributeMaxDynamicSharedMemorySize,
                             SMEM_MMA_BYTES);
        attr_set = true;
    }

    int e4 = (E + 3) / 4;

    // CSR build (self-loops + accumulator zeroing folded into scan;
    // g_deg self-restores to zero each call)
    k_count<<<(e4 + 255) / 256, 256>>>(ei, E);
    k_scan2<<<1, 1024>>>(N);
    k_fill<<<(e4 + 255) / 256, 256>>>(ei, E);

    // Layer 1: [xl1 | xr1] = x @ [Wl1 | Wr1]  (M=N, K=128, H=256, 2H=512)
    {
        dim3 grid((N + 63) / 64, 4);
        k_mma<<<grid, 256, SMEM_MMA_BYTES>>>(x, Wl1, Wr1, xl1, xr1, N, 128, 256);
    }
    // GATv2 layer 1 (H=8, C=32) + bias + ELU
    k_node_agg<256, 8, 4, true, false><<<(N * 32 + 255) / 256, 256>>>(xl1, xr1, att1, b1, h1, N);

    // Layer 2: [xl2 | xr2] = h1 @ [Wl2 | Wr2]  (M=N, K=256, H=64, 2H=128)
    {
        dim3 grid((N + 63) / 64, 1);
        k_mma<<<grid, 256, SMEM_MMA_BYTES>>>(h1, Wl2, Wr2, xl2, xr2, N, 256, 64);
    }
    // GATv2 layer 2 (H=1, C=64) + bias + fused InstanceNorm stats
    k_node_agg<64, 2, 32, false, true><<<(N * 32 + 255) / 256, 256>>>(xl2, xr2, att2, b2, h2, N);

    // InstanceNorm normalize + log_softmax
    k_final<<<(N * 32 + 255) / 256, 256>>>(h2, gamma, beta, (float*)d_out, N);
}

// round 9
// speedup vs baseline: 1.0087x; 1.0087x over previous
#include <cuda_runtime.h>
#include <cstdint>
#include <cstdio>

// Problem-size capacities (from reference setup: N=20000, E=320000)
#define NMAXN 20000
#define EMAXE 320000
#define ETOT  (NMAXN + EMAXE)

// ---------------- static device scratch (no allocations allowed) ----------------
// g_deg is SELF-RESTORING: zero-initialized at load, and k_scan2 re-zeroes it
// after consuming it, so every kernel_launch call starts from the same state.
__device__ __align__(16) float g_xl1[NMAXN * 256];
__device__ __align__(16) float g_xr1[NMAXN * 256];
__device__ __align__(16) float g_h1 [NMAXN * 256];
__device__ __align__(16) float g_xl2[NMAXN * 64];
__device__ __align__(16) float g_xr2[NMAXN * 64];
__device__ __align__(16) float g_h2 [NMAXN * 64];
__device__ int   g_deg[NMAXN];         // starts zeroed; restored by k_scan2
__device__ int   g_off[NMAXN + 1];
__device__ int   g_cur[NMAXN];
__device__ int   g_csrc[ETOT];
__device__ float g_sum[64];
__device__ float g_sumsq[64];

// ---------------- CSR build (by dst), E edges, 4 edges/thread ----------------
__global__ void k_count(const int* __restrict__ ei, int E) {
    int i0 = (blockIdx.x * blockDim.x + threadIdx.x) * 4;
    if (i0 + 4 <= E && ((E & 3) == 0)) {
        int4 d = *reinterpret_cast<const int4*>(ei + E + i0);
        atomicAdd(&g_deg[d.x], 1);
        atomicAdd(&g_deg[d.y], 1);
        atomicAdd(&g_deg[d.z], 1);
        atomicAdd(&g_deg[d.w], 1);
    } else {
        #pragma unroll
        for (int j = 0; j < 4; j++) {
            int i = i0 + j;
            if (i < E) atomicAdd(&g_deg[__ldg(ei + E + i)], 1);
        }
    }
}

// single-block chunked scan of (g_deg[i] + 1) -> offsets (self-loop folded in).
// Writes the self-loop into slot 0, sets g_cur = off + 1, zeroes g_deg behind
// itself, and zeroes the InstanceNorm accumulators.
#define SCAN_PER ((NMAXN + 1023) / 1024)
__global__ __launch_bounds__(1024) void k_scan2(int N) {
    __shared__ int sh[1024];
    int tid = threadIdx.x;
    if (tid < 64) { g_sum[tid] = 0.f; g_sumsq[tid] = 0.f; }
    int base = tid * SCAN_PER;
    int vals[SCAN_PER];
    int s = 0;
    #pragma unroll
    for (int i = 0; i < SCAN_PER; i++) {
        int idx = base + i;
        int v = 0;
        if (idx < N) {
            v = g_deg[idx] + 1;      // +1 = self-loop
            g_deg[idx] = 0;          // restore for next call
        }
        vals[i] = s;                 // exclusive within chunk
        s += v;
    }
    sh[tid] = s;
    __syncthreads();
    #pragma unroll
    for (int o = 1; o < 1024; o <<= 1) {
        int t = (tid >= o) ? sh[tid - o] : 0;
        __syncthreads();
        sh[tid] += t;
        __syncthreads();
    }
    int block_excl = sh[tid] - s;
    #pragma unroll
    for (int i = 0; i < SCAN_PER; i++) {
        int idx = base + i;
        if (idx < N) {
            int o = block_excl + vals[i];
            g_off[idx] = o;
            g_csrc[o] = idx;         // self-loop occupies slot 0
            g_cur[idx] = o + 1;
        }
    }
    if (tid == 1023) g_off[N] = sh[1023];
}

__global__ void k_fill(const int* __restrict__ ei, int E) {
    int i0 = (blockIdx.x * blockDim.x + threadIdx.x) * 4;
    if (i0 + 4 <= E && ((E & 3) == 0)) {
        int4 sv = *reinterpret_cast<const int4*>(ei + i0);
        int4 dv = *reinterpret_cast<const int4*>(ei + E + i0);
        int p0 = atomicAdd(&g_cur[dv.x], 1);
        int p1 = atomicAdd(&g_cur[dv.y], 1);
        int p2 = atomicAdd(&g_cur[dv.z], 1);
        int p3 = atomicAdd(&g_cur[dv.w], 1);
        g_csrc[p0] = sv.x;
        g_csrc[p1] = sv.y;
        g_csrc[p2] = sv.z;
        g_csrc[p3] = sv.w;
    } else {
        #pragma unroll
        for (int j = 0; j < 4; j++) {
            int i = i0 + j;
            if (i < E) {
                int src = __ldg(ei + i);
                int dst = __ldg(ei + E + i);
                int pos = atomicAdd(&g_cur[dst], 1);
                g_csrc[pos] = src;
            }
        }
    }
}

// ---------------- tf32 tensor-core GEMM, cp.async double-buffered ----------------
__device__ __forceinline__ unsigned f2tf32(float f) {
    unsigned u;
    asm("cvt.rna.tf32.f32 %0, %1;" : "=r"(u) : "f"(f));
    return u;
}

__device__ __forceinline__ void mma_tf32(float* d, const unsigned* a, unsigned b0, unsigned b1) {
    asm volatile(
        "mma.sync.aligned.m16n8k8.row.col.f32.tf32.tf32.f32 "
        "{%0,%1,%2,%3}, {%4,%5,%6,%7}, {%8,%9}, {%0,%1,%2,%3};"
        : "+f"(d[0]), "+f"(d[1]), "+f"(d[2]), "+f"(d[3])
        : "r"(a[0]), "r"(a[1]), "r"(a[2]), "r"(a[3]), "r"(b0), "r"(b1));
}

__device__ __forceinline__ void cp_async16(uint32_t saddr, const void* g, int srcbytes) {
    asm volatile("cp.async.cg.shared.global [%0], [%1], 16, %2;"
                 :: "r"(saddr), "l"(g), "r"(srcbytes));
}

#define AS_STRIDE 36
#define BS_STRIDE 136
#define AS_STAGE  (64 * AS_STRIDE)
#define BS_STAGE  (32 * BS_STRIDE)
#define SMEM_MMA_BYTES ((2 * AS_STAGE + 2 * BS_STAGE) * 4)

__global__ __launch_bounds__(256, 4) void k_mma(
    const float* __restrict__ A,
    const float* __restrict__ B0, const float* __restrict__ B1,
    float* __restrict__ C0, float* __restrict__ C1,
    int M, int K, int H)
{
    extern __shared__ float smem[];
    float* sAs = smem;                       // [2][64][36]
    float* sBs = smem + 2 * AS_STAGE;        // [2][32][136]

    int tid = threadIdx.x;
    int lane = tid & 31, warp = tid >> 5;
    int wm = warp & 1, wn = warp >> 1;       // 2 x 4 warp grid
    int m0 = blockIdx.x * 64;
    int n0g = blockIdx.y * 128;              // col in concatenated [0, 2H) space
    int g = lane >> 2, tg = lane & 3;

    float acc[2][4][4];
    #pragma unroll
    for (int mt = 0; mt < 2; mt++)
        #pragma unroll
        for (int nt = 0; nt < 4; nt++)
            #pragma unroll
            for (int i = 0; i < 4; i++) acc[mt][nt][i] = 0.f;

    int ar = tid >> 2;          // 0..63
    int ac = (tid & 3) * 8;     // 0,8,16,24
    int br = tid >> 3;          // 0..31
    int bc = (tid & 7) * 16;    // 0..112

    int arow = m0 + ar;
    int apred = (arow < M) ? 16 : 0;
    if (arow >= M) arow = M - 1;
    const float* abase = A + (size_t)arow * K + ac;

    const float* bsrc[4];
    #pragma unroll
    for (int i = 0; i < 4; i++) {
        int col = n0g + bc + i * 4;
        bsrc[i] = (col < H) ? (B0 + (size_t)br * H + col)
                            : (B1 + (size_t)br * H + (col - H));
    }

    uint32_t sA0 = (uint32_t)__cvta_generic_to_shared(sAs);
    uint32_t sB0 = (uint32_t)__cvta_generic_to_shared(sBs);

    int nIter = K >> 5;

    auto load_stage = [&](int k0, int st) {
        uint32_t sa = sA0 + (st * AS_STAGE + ar * AS_STRIDE + ac) * 4;
        const float* ap = abase + k0;
        cp_async16(sa,      ap,     apred);
        cp_async16(sa + 16, ap + 4, apred);
        uint32_t sb = sB0 + (st * BS_STAGE + br * BS_STRIDE + bc) * 4;
        size_t koff = (size_t)k0 * H;
        #pragma unroll
        for (int i = 0; i < 4; i++)
            cp_async16(sb + i * 16, bsrc[i] + koff, 16);
    };

    load_stage(0, 0);
    asm volatile("cp.async.commit_group;" ::: "memory");

    for (int it = 0; it < nIter; it++) {
        int st = it & 1;
        asm volatile("cp.async.wait_group 0;" ::: "memory");
        __syncthreads();
        if (it + 1 < nIter) {
            load_stage((it + 1) << 5, st ^ 1);
            asm volatile("cp.async.commit_group;" ::: "memory");
        }

        const float* As = sAs + st * AS_STAGE;
        const float* Bs = sBs + st * BS_STAGE;

        #pragma unroll
        for (int kk = 0; kk < 32; kk += 8) {
            unsigned afr[2][4];
            #pragma unroll
            for (int mt = 0; mt < 2; mt++) {
                int row = wm * 32 + mt * 16;
                afr[mt][0] = f2tf32(As[(row + g    ) * AS_STRIDE + kk + tg    ]);
                afr[mt][1] = f2tf32(As[(row + g + 8) * AS_STRIDE + kk + tg    ]);
                afr[mt][2] = f2tf32(As[(row + g    ) * AS_STRIDE + kk + tg + 4]);
                afr[mt][3] = f2tf32(As[(row + g + 8) * AS_STRIDE + kk + tg + 4]);
            }
            #pragma unroll
            for (int nt = 0; nt < 4; nt++) {
                int ncol = wn * 32 + nt * 8;
                unsigned b0 = f2tf32(Bs[(kk + tg    ) * BS_STRIDE + ncol + g]);
                unsigned b1 = f2tf32(Bs[(kk + tg + 4) * BS_STRIDE + ncol + g]);
                #pragma unroll
                for (int mt = 0; mt < 2; mt++)
                    mma_tf32(acc[mt][nt], afr[mt], b0, b1);
            }
        }
        __syncthreads();
    }

    #pragma unroll
    for (int mt = 0; mt < 2; mt++) {
        int r0 = m0 + wm * 32 + mt * 16 + g;
        #pragma unroll
        for (int nt = 0; nt < 4; nt++) {
            int col = n0g + wn * 32 + nt * 8 + tg * 2;
            float* Cp = C0;
            int c = col;
            if (col >= H) { Cp = C1; c = col - H; }
            if (r0 < M)
                *reinterpret_cast<float2*>(Cp + (size_t)r0 * H + c) =
                    make_float2(acc[mt][nt][0], acc[mt][nt][1]);
            if (r0 + 8 < M)
                *reinterpret_cast<float2*>(Cp + (size_t)(r0 + 8) * H + c) =
                    make_float2(acc[mt][nt][2], acc[mt][nt][3]);
        }
    }
}

// ---------------- vector load helper ----------------
template <int V>
__device__ __forceinline__ void loadv(float* d, const float* __restrict__ p) {
    if constexpr (V == 8) {
        float4 a = *reinterpret_cast<const float4*>(p);
        float4 b = *reinterpret_cast<const float4*>(p + 4);
        d[0] = a.x; d[1] = a.y; d[2] = a.z; d[3] = a.w;
        d[4] = b.x; d[5] = b.y; d[6] = b.z; d[7] = b.w;
    } else if constexpr (V == 2) {
        float2 a = *reinterpret_cast<const float2*>(p);
        d[0] = a.x; d[1] = a.y;
    } else {
        #pragma unroll
        for (int j = 0; j < V; j++) d[j] = p[j];
    }
}

// ---------------- GATv2 node aggregation: warp per node, online softmax ----------------
// 2-edge unrolled mainloop (R7-proven config), branchy single-edge tail.
template <int HC, int VPT, int REDW, bool ELU_ACT, bool STATS>
__global__ __launch_bounds__(256) void k_node_agg(
    const float* __restrict__ xl, const float* __restrict__ xr,
    const float* __restrict__ att, const float* __restrict__ bias,
    float* __restrict__ outp, int N)
{
    __shared__ float sh_sum[STATS ? 64 : 1];
    __shared__ float sh_sq [STATS ? 64 : 1];
    int tid = threadIdx.x;
    if (STATS) {
        if (tid < 64) { sh_sum[tid] = 0.f; sh_sq[tid] = 0.f; }
        __syncthreads();
    }

    int warp = (blockIdx.x * blockDim.x + tid) >> 5;
    int lane = tid & 31;
    bool active = warp < N;
    int c0 = lane * VPT;

    if (active) {
        int n = warp;
        float xrv[VPT], attv[VPT], acc[VPT];
        loadv<VPT>(xrv, xr + (size_t)n * HC + c0);
        loadv<VPT>(attv, att + c0);
        #pragma unroll
        for (int j = 0; j < VPT; j++) acc[j] = 0.f;

        float m = __int_as_float(0xff800000);   // -inf
        float denom = 0.f;

        int s = g_off[n], e = g_off[n + 1];
        int i = s;
        for (; i + 2 <= e; i += 2) {
            int s0 = g_csrc[i];
            int s1 = g_csrc[i + 1];
            float xlv0[VPT], xlv1[VPT];
            loadv<VPT>(xlv0, xl + (size_t)s0 * HC + c0);
            loadv<VPT>(xlv1, xl + (size_t)s1 * HC + c0);

            float sc0 = 0.f, sc1 = 0.f;
            #pragma unroll
            for (int j = 0; j < VPT; j++) {
                float t0 = xlv0[j] + xrv[j];
                float t1 = xlv1[j] + xrv[j];
                t0 = (t0 > 0.f) ? t0 : 0.2f * t0;
                t1 = (t1 > 0.f) ? t1 : 0.2f * t1;
                sc0 = fmaf(t0, attv[j], sc0);
                sc1 = fmaf(t1, attv[j], sc1);
            }
            #pragma unroll
            for (int w = 1; w < REDW; w <<= 1) {
                sc0 += __shfl_xor_sync(0xffffffffu, sc0, w);
                sc1 += __shfl_xor_sync(0xffffffffu, sc1, w);
            }

            // exact fused pair update
            float newm = fmaxf(m, fmaxf(sc0, sc1));
            float r  = __expf(m - newm);       // 0 on first iter (m = -inf)
            float e0 = __expf(sc0 - newm);
            float e1 = __expf(sc1 - newm);
            denom = fmaf(denom, r, e0 + e1);
            #pragma unroll
            for (int j = 0; j < VPT; j++)
                acc[j] = fmaf(acc[j], r, fmaf(e0, xlv0[j], e1 * xlv1[j]));
            m = newm;
        }
        if (i < e) {                            // tail edge (branchy update)
            int src = g_csrc[i];
            float xlv[VPT];
            loadv<VPT>(xlv, xl + (size_t)src * HC + c0);
            float sc = 0.f;
            #pragma unroll
            for (int j = 0; j < VPT; j++) {
                float t = xlv[j] + xrv[j];
                t = (t > 0.f) ? t : 0.2f * t;
                sc = fmaf(t, attv[j], sc);
            }
            #pragma unroll
            for (int w = 1; w < REDW; w <<= 1)
                sc += __shfl_xor_sync(0xffffffffu, sc, w);
            if (sc > m) {
                float r = __expf(m - sc);
                denom *= r;
                #pragma unroll
                for (int j = 0; j < VPT; j++) acc[j] *= r;
                m = sc;
            }
            float ex = __expf(sc - m);
            denom += ex;
            #pragma unroll
            for (int j = 0; j < VPT; j++) acc[j] = fmaf(ex, xlv[j], acc[j]);
        }

        float inv = 1.f / (denom + 1e-16f);
        #pragma unroll
        for (int j = 0; j < VPT; j++) {
            float v = acc[j] * inv + bias[c0 + j];
            if (ELU_ACT) v = (v > 0.f) ? v : (__expf(v) - 1.f);  // ELU alpha=1
            outp[(size_t)n * HC + c0 + j] = v;
            if (STATS) {
                atomicAdd(&sh_sum[c0 + j], v);
                atomicAdd(&sh_sq [c0 + j], v * v);
            }
        }
    }

    if (STATS) {
        __syncthreads();
        if (tid < 64) {
            atomicAdd(&g_sum[tid],   sh_sum[tid]);
            atomicAdd(&g_sumsq[tid], sh_sq[tid]);
        }
    }
}

// ---------------- InstanceNorm + log_softmax epilogue (warp per node) ----------------
__global__ __launch_bounds__(256) void k_final(
    const float* __restrict__ h,
    const float* __restrict__ gamma, const float* __restrict__ beta,
    float* __restrict__ out, int N)
{
    int gw = (blockIdx.x * blockDim.x + threadIdx.x) >> 5;
    int lane = threadIdx.x & 31;
    if (gw >= N) return;
    int c0 = lane * 2;

    float2 x = *reinterpret_cast<const float2*>(h + (size_t)gw * 64 + c0);
    float invN = 1.f / (float)N;

    float mean0 = g_sum[c0] * invN;
    float var0  = g_sumsq[c0] * invN - mean0 * mean0;
    float y0 = (x.x - mean0) * rsqrtf(var0 + 1e-5f) * gamma[c0] + beta[c0];

    float mean1 = g_sum[c0 + 1] * invN;
    float var1  = g_sumsq[c0 + 1] * invN - mean1 * mean1;
    float y1 = (x.y - mean1) * rsqrtf(var1 + 1e-5f) * gamma[c0 + 1] + beta[c0 + 1];

    float2 yv = make_float2(y0, y1);
    *reinterpret_cast<float2*>(out + (size_t)gw * 64 + c0) = yv;

    float mx = fmaxf(y0, y1);
    #pragma unroll
    for (int w = 1; w < 32; w <<= 1) mx = fmaxf(mx, __shfl_xor_sync(0xffffffffu, mx, w));
    float se = __expf(y0 - mx) + __expf(y1 - mx);
    #pragma unroll
    for (int w = 1; w < 32; w <<= 1) se += __shfl_xor_sync(0xffffffffu, se, w);
    float ls = __logf(se) + mx;          // log-sum-exp

    float2 lv = make_float2(y0 - ls, y1 - ls);
    *reinterpret_cast<float2*>(out + (size_t)N * 64 + (size_t)gw * 64 + c0) = lv;
}

// ---------------- host launcher ----------------
extern "C" void kernel_launch(void* const* d_in, const int* in_sizes, int n_in,
                              void* d_out, int out_size)
{
    const float* x     = (const float*)d_in[0];
    const float* Wl1   = (const float*)d_in[1];
    const float* Wr1   = (const float*)d_in[2];
    const float* att1  = (const float*)d_in[3];
    const float* b1    = (const float*)d_in[4];
    const float* Wl2   = (const float*)d_in[5];
    const float* Wr2   = (const float*)d_in[6];
    const float* att2  = (const float*)d_in[7];
    const float* b2    = (const float*)d_in[8];
    const float* gamma = (const float*)d_in[9];
    const float* beta  = (const float*)d_in[10];
    const int*   ei    = (const int*)  d_in[11];   // [2, E] int32

    int N = in_sizes[0] / 128;
    int E = in_sizes[11] / 2;

    void *p;
    cudaGetSymbolAddress(&p, g_xl1); float* xl1 = (float*)p;
    cudaGetSymbolAddress(&p, g_xr1); float* xr1 = (float*)p;
    cudaGetSymbolAddress(&p, g_h1 ); float* h1  = (float*)p;
    cudaGetSymbolAddress(&p, g_xl2); float* xl2 = (float*)p;
    cudaGetSymbolAddress(&p, g_xr2); float* xr2 = (float*)p;
    cudaGetSymbolAddress(&p, g_h2 ); float* h2  = (float*)p;

    static bool attr_set = false;
    if (!attr_set) {
        cudaFuncSetAttribute(k_mma, cudaFuncAttributeMaxDynamicSharedMemorySize,
                             SMEM_MMA_BYTES);
        attr_set = true;
    }

    int e4 = (E + 3) / 4;

    // CSR build (self-loops + accumulator zeroing folded into scan;
    // g_deg self-restores to zero each call)
    k_count<<<(e4 + 255) / 256, 256>>>(ei, E);
    k_scan2<<<1, 1024>>>(N);
    k_fill<<<(e4 + 255) / 256, 256>>>(ei, E);

    // Layer 1: [xl1 | xr1] = x @ [Wl1 | Wr1]  (M=N, K=128, H=256, 2H=512)
    {
        dim3 grid((N + 63) / 64, 4);
        k_mma<<<grid, 256, SMEM_MMA_BYTES>>>(x, Wl1, Wr1, xl1, xr1, N, 128, 256);
    }
    // GATv2 layer 1 (H=8, C=32) + bias + ELU
    k_node_agg<256, 8, 4, true, false><<<(N * 32 + 255) / 256, 256>>>(xl1, xr1, att1, b1, h1, N);

    // Layer 2: [xl2 | xr2] = h1 @ [Wl2 | Wr2]  (M=N, K=256, H=64, 2H=128)
    {
        dim3 grid((N + 63) / 64, 1);
        k_mma<<<grid, 256, SMEM_MMA_BYTES>>>(h1, Wl2, Wr2, xl2, xr2, N, 256, 64);
    }
    // GATv2 layer 2 (H=1, C=64) + bias + fused InstanceNorm stats
    k_node_agg<64, 2, 32, false, true><<<(N * 32 + 255) / 256, 256>>>(xl2, xr2, att2, b2, h2, N);

    // InstanceNorm normalize + log_softmax
    k_final<<<(N * 32 + 255) / 256, 256>>>(h2, gamma, beta, (float*)d_out, N);
}